// round 8
// baseline (speedup 1.0000x reference)
#include <cuda_runtime.h>
#include <cuda_fp16.h>
#include <math.h>

#define BATCH 64
#define NROW  307
#define NN    614
#define D     64
#define XST   68   // smem tile stride (conflict-free for mma frag loads)
#define MAXD  128  // max node degree bound (observed ~35; 128 = huge margin)

// Scratch (device globals — allocation-free per harness rules)
__device__ __align__(16) __half g_Whh[(size_t)BATCH * NN * D];   // [b][m][c] fp16
__device__ float2  g_l1[NN * BATCH];               // [n][b] = {Wh1, exp(Wh1)}
__device__ float2  g_l2[NN * BATCH];               // [m][b] = {Wh2, exp(Wh2)}
__device__ float   g_att[(size_t)NN * MAXD * BATCH]; // [m][p][b] normalized att
__device__ int     g_row_idx[NN * NN];
__device__ int     g_row_cnt[NN];
__device__ int     g_col_idx[NN * NN];
__device__ int     g_col_cnt[NN];
__device__ int     g_pos[NN * NN];                 // [m][n] -> p (col position)

__device__ __forceinline__ unsigned cvt_tf32(float f) {
    unsigned r; asm("cvt.rna.tf32.f32 %0, %1;" : "=r"(r) : "f"(f)); return r;
}
__device__ __forceinline__ void mma_tf32(float c[4], unsigned a0, unsigned a1,
                                         unsigned a2, unsigned a3,
                                         unsigned b0, unsigned b1) {
    asm("mma.sync.aligned.m16n8k8.row.col.f32.tf32.tf32.f32 "
        "{%0,%1,%2,%3},{%4,%5,%6,%7},{%8,%9},{%0,%1,%2,%3};"
        : "+f"(c[0]), "+f"(c[1]), "+f"(c[2]), "+f"(c[3])
        : "r"(a0), "r"(a1), "r"(a2), "r"(a3), "r"(b0), "r"(b1));
}
__device__ __forceinline__ void fma8(float acc[8], float w, uint4 raw) {
    float2 f0 = __half22float2(*(const __half2*)&raw.x);
    float2 f1 = __half22float2(*(const __half2*)&raw.y);
    float2 f2 = __half22float2(*(const __half2*)&raw.z);
    float2 f3 = __half22float2(*(const __half2*)&raw.w);
    acc[0] = fmaf(w, f0.x, acc[0]); acc[1] = fmaf(w, f0.y, acc[1]);
    acc[2] = fmaf(w, f1.x, acc[2]); acc[3] = fmaf(w, f1.y, acc[3]);
    acc[4] = fmaf(w, f2.x, acc[4]); acc[5] = fmaf(w, f2.y, acc[5]);
    acc[6] = fmaf(w, f3.x, acc[6]); acc[7] = fmaf(w, f3.y, acc[7]);
}

// ---------------------------------------------------------------------------
// Kernel 0: row-CSR + col-CSR of (adj>0); col pass also scatters g_pos[m][n].
// ---------------------------------------------------------------------------
__global__ __launch_bounds__(1024) void k_csr(const float* __restrict__ adj) {
    const int tid  = threadIdx.x;
    const int lane = tid & 31;
    const int w    = tid >> 5;               // warp 0..31
    if (blockIdx.y == 0) {
        const int r = blockIdx.x * 32 + w;
        if (r >= NN) return;
        int cnt = 0;
        for (int m0 = 0; m0 < NN; m0 += 32) {
            int m = m0 + lane;
            float v = (m < NN) ? adj[r * NN + m] : 0.f;
            unsigned msk = __ballot_sync(0xffffffffu, v > 0.f);
            if (v > 0.f)
                g_row_idx[r * NN + cnt + __popc(msk & ((1u << lane) - 1u))] = m;
            cnt += __popc(msk);
        }
        if (lane == 0) g_row_cnt[r] = cnt;
    } else {
        __shared__ float tile[32][33];
        const int cbase = blockIdx.x * 32;
        const int c = cbase + w;              // this warp's column
        int cnt = 0;
        for (int n0 = 0; n0 < NN; n0 += 32) {
            int n = n0 + w, m = cbase + lane;
            tile[w][lane] = (n < NN && m < NN) ? adj[n * NN + m] : 0.f;
            __syncthreads();
            if (c < NN) {
                float v = tile[lane][w];
                unsigned msk = __ballot_sync(0xffffffffu, v > 0.f);
                if (v > 0.f) {
                    int p = cnt + __popc(msk & ((1u << lane) - 1u));
                    g_col_idx[c * NN + p] = n0 + lane;
                    g_pos[c * NN + n0 + lane] = p;
                }
                cnt += __popc(msk);
            }
            __syncthreads();
        }
        if (c < NN && lane == 0) g_col_cnt[c] = cnt;
    }
}

// ---------------------------------------------------------------------------
// Kernel 1: Wh = concat(ht,h)@W via tf32 mma (stored fp16); exact fp32 logits
// stored batch-minor as {val, exp(val)} pairs for separable softmax weights.
// ---------------------------------------------------------------------------
__global__ __launch_bounds__(128) void k_wh(const float* __restrict__ h,
                                            const float* __restrict__ ht,
                                            const float* __restrict__ W,
                                            const float* __restrict__ a) {
    const int b     = blockIdx.y;
    const int rbase = blockIdx.x * 64;
    const int tid   = threadIdx.x;

    __shared__ float xs[64 * XST];
    __shared__ float Ws[64 * XST];
    __shared__ float Wa[128];

    for (int k = tid; k < 1024; k += 128) {
        int i = k >> 4, c4 = (k & 15) * 4;
        *(float4*)&Ws[i * XST + c4] = *(const float4*)&W[i * 64 + c4];
    }
    for (int k = tid; k < 1024; k += 128) {
        int r = k >> 4, c4 = (k & 15) * 4;
        int gr = rbase + r;
        float4 v = make_float4(0.f, 0.f, 0.f, 0.f);
        if (gr < NN) {
            const float* src = (gr < NROW) ? &ht[((size_t)b * NROW + gr) * D]
                                           : &h [((size_t)b * NROW + gr - NROW) * D];
            v = *(const float4*)(src + c4);
        }
        *(float4*)&xs[r * XST + c4] = v;
    }
    __syncthreads();

    {   // Wa[0:64] = W@a[:64], Wa[64:128] = W@a[64:]
        int kk = tid & 63, which = tid >> 6;
        float s = 0.f;
        for (int c = 0; c < 64; c++)
            s = fmaf(Ws[kk * XST + c], a[which * 64 + c], s);
        Wa[which * 64 + kk] = s;
    }
    __syncthreads();

    const int warp = tid >> 5, lane = tid & 31;
    const int g = lane >> 2, t4 = lane & 3;
    const int m0 = warp * 16;
    float acc[8][4];
#pragma unroll
    for (int nt = 0; nt < 8; nt++)
#pragma unroll
        for (int j = 0; j < 4; j++) acc[nt][j] = 0.f;

#pragma unroll
    for (int ks = 0; ks < 64; ks += 8) {
        unsigned A0 = cvt_tf32(xs[(m0 + g)     * XST + ks + t4]);
        unsigned A1 = cvt_tf32(xs[(m0 + g + 8) * XST + ks + t4]);
        unsigned A2 = cvt_tf32(xs[(m0 + g)     * XST + ks + t4 + 4]);
        unsigned A3 = cvt_tf32(xs[(m0 + g + 8) * XST + ks + t4 + 4]);
#pragma unroll
        for (int nt = 0; nt < 8; nt++) {
            unsigned B0 = cvt_tf32(Ws[(ks + t4)     * XST + nt * 8 + g]);
            unsigned B1 = cvt_tf32(Ws[(ks + t4 + 4) * XST + nt * 8 + g]);
            mma_tf32(acc[nt], A0, A1, A2, A3, B0, B1);
        }
    }

#pragma unroll
    for (int nt = 0; nt < 8; nt++) {
        int col = nt * 8 + t4 * 2;
        int r0 = rbase + m0 + g, r1 = r0 + 8;
        __half2 h0 = __floats2half2_rn(acc[nt][0], acc[nt][1]);
        __half2 h1 = __floats2half2_rn(acc[nt][2], acc[nt][3]);
        if (r0 < NN) *(__half2*)&g_Whh[((size_t)b * NN + r0) * D + col] = h0;
        if (r1 < NN) *(__half2*)&g_Whh[((size_t)b * NN + r1) * D + col] = h1;
    }

    {   // Exact fp32 logits + their exps (separable softmax numerators)
        int r = tid & 63, which = tid >> 6;
        float s = 0.f;
#pragma unroll 4
        for (int k2 = 0; k2 < 64; k2++)
            s = fmaf(xs[r * XST + k2], Wa[which * 64 + k2], s);
        int gr = rbase + r;
        if (gr < NN) {
            float2 v = make_float2(s, __expf(s));
            if (which == 0) g_l1[gr * BATCH + b] = v;
            else            g_l2[gr * BATCH + b] = v;
        }
    }
}

// ---------------------------------------------------------------------------
// Kernel 2: normalized attention table — barrier-free. One column m per
// block, 64 threads (thread = batch b). Z accumulates serially per thread;
// pass 2 rescales this thread's own writes (same-address RAW, no fence).
// ---------------------------------------------------------------------------
__global__ __launch_bounds__(64) void k_att() {
    const int m = blockIdx.x;
    const int b = threadIdx.x;               // 0..63
    const int cnt = g_col_cnt[m];
    const float2 l2 = g_l2[m * BATCH + b];
    const int* __restrict__ ci = &g_col_idx[m * NN];
    float* dst = &g_att[(size_t)m * MAXD * BATCH + b];

    float Z = 0.f;
    for (int p = 0; p < cnt; p++) {
        float2 l1 = g_l1[ci[p] * BATCH + b];
        float s = l1.x + l2.x;
        float ew = (s > 0.f) ? l1.y * l2.y : __expf(0.2f * s);
        dst[p * BATCH] = ew;
        Z += ew;
    }
    const float zi = 1.f / Z;
    for (int p = 0; p < cnt; p++)
        dst[p * BATCH] *= zi;
}

// ---------------------------------------------------------------------------
// Kernel 3: h_prime[b,n,:] = sum_j att * Wh[b,m_j,:]; concat + ELU.
// 512 threads = 64 batches x 8 lanes, one n per block. No exp:
// weight is a broadcast LDG from the precomputed normalized table.
// ---------------------------------------------------------------------------
__global__ __launch_bounds__(512) void k_out(float* __restrict__ out) {
    const int n    = blockIdx.x;
    const int tid  = threadIdx.x;
    const int b    = tid >> 3;        // 0..63
    const int lane = tid & 7;
    const int cnt  = g_row_cnt[n];

    __shared__ int2 sjd[MAXD];        // {wh byte-off, att index base}
    if (tid < cnt) {
        int m = g_row_idx[n * NN + tid];
        int p = g_pos[m * NN + n];
        sjd[tid] = make_int2(m << 7, (m * MAXD + p) * BATCH);
    }
    __syncthreads();

    const char* whb = (const char*)g_Whh + (size_t)b * NN * 128 + lane * 16;

    float acc[8];
#pragma unroll
    for (int k = 0; k < 8; k++) acc[k] = 0.f;

    int j = 0;
    for (; j + 4 <= cnt; j += 4) {
        int2 d0 = sjd[j + 0], d1 = sjd[j + 1], d2 = sjd[j + 2], d3 = sjd[j + 3];
        float w0 = g_att[d0.y + b];
        float w1 = g_att[d1.y + b];
        float w2 = g_att[d2.y + b];
        float w3 = g_att[d3.y + b];
        uint4 r0 = *(const uint4*)(whb + d0.x);
        uint4 r1 = *(const uint4*)(whb + d1.x);
        uint4 r2 = *(const uint4*)(whb + d2.x);
        uint4 r3 = *(const uint4*)(whb + d3.x);
        fma8(acc, w0, r0); fma8(acc, w1, r1);
        fma8(acc, w2, r2); fma8(acc, w3, r3);
    }
    for (; j < cnt; j++) {
        int2 d = sjd[j];
        float w = g_att[d.y + b];
        uint4 r = *(const uint4*)(whb + d.x);
        fma8(acc, w, r);
    }

#pragma unroll
    for (int k = 0; k < 8; k++)
        acc[k] = (acc[k] > 0.f) ? acc[k] : (__expf(acc[k]) - 1.f);

    size_t ob = (n < NROW) ? (((size_t)b * NROW + n) * 128 + lane * 8)
                           : (((size_t)b * NROW + (n - NROW)) * 128 + 64 + lane * 8);
    *(float4*)(out + ob)     = make_float4(acc[0], acc[1], acc[2], acc[3]);
    *(float4*)(out + ob + 4) = make_float4(acc[4], acc[5], acc[6], acc[7]);
}

// ---------------------------------------------------------------------------
extern "C" void kernel_launch(void* const* d_in, const int* in_sizes, int n_in,
                              void* d_out, int out_size) {
    const float* h   = (const float*)d_in[0];
    const float* ht  = (const float*)d_in[1];
    const float* W   = (const float*)d_in[2];
    const float* a   = (const float*)d_in[3];
    const float* adj = (const float*)d_in[4];
    float* out = (float*)d_out;

    k_csr<<<dim3((NN + 31) / 32, 2), 1024>>>(adj);
    k_wh<<<dim3((NN + 63) / 64, BATCH), 128>>>(h, ht, W, a);
    k_att<<<NN, 64>>>();
    k_out<<<NN, 512>>>(out);
}

// round 9
// speedup vs baseline: 1.0471x; 1.0471x over previous
#include <cuda_runtime.h>
#include <cuda_fp16.h>
#include <math.h>

#define BATCH 64
#define NROW  307
#define NN    614
#define D     64
#define XST   68   // smem tile stride (conflict-free for mma frag loads)
#define MAXD  128  // max node degree bound (observed ~35; 128 = huge margin)

// Scratch (device globals — allocation-free per harness rules)
__device__ __align__(16) __half g_Whh[(size_t)BATCH * NN * D];   // [b][m][c] fp16
__device__ float2  g_l1[NN * BATCH];               // [n][b] = {Wh1, exp(Wh1)}
__device__ float2  g_l2[NN * BATCH];               // [m][b] = {Wh2, exp(Wh2)}
__device__ float   g_att[(size_t)NN * MAXD * BATCH]; // [m][p][b] normalized att
__device__ int     g_row_idx[NN * NN];
__device__ int     g_row_cnt[NN];
__device__ int     g_col_idx[NN * NN];
__device__ int     g_col_cnt[NN];
__device__ int     g_pos[NN * NN];                 // [m][n] -> p (col position)

__device__ __forceinline__ unsigned cvt_tf32(float f) {
    unsigned r; asm("cvt.rna.tf32.f32 %0, %1;" : "=r"(r) : "f"(f)); return r;
}
__device__ __forceinline__ void mma_tf32(float c[4], unsigned a0, unsigned a1,
                                         unsigned a2, unsigned a3,
                                         unsigned b0, unsigned b1) {
    asm("mma.sync.aligned.m16n8k8.row.col.f32.tf32.tf32.f32 "
        "{%0,%1,%2,%3},{%4,%5,%6,%7},{%8,%9},{%0,%1,%2,%3};"
        : "+f"(c[0]), "+f"(c[1]), "+f"(c[2]), "+f"(c[3])
        : "r"(a0), "r"(a1), "r"(a2), "r"(a3), "r"(b0), "r"(b1));
}
__device__ __forceinline__ void fma8(float acc[8], float w, uint4 raw) {
    float2 f0 = __half22float2(*(const __half2*)&raw.x);
    float2 f1 = __half22float2(*(const __half2*)&raw.y);
    float2 f2 = __half22float2(*(const __half2*)&raw.z);
    float2 f3 = __half22float2(*(const __half2*)&raw.w);
    acc[0] = fmaf(w, f0.x, acc[0]); acc[1] = fmaf(w, f0.y, acc[1]);
    acc[2] = fmaf(w, f1.x, acc[2]); acc[3] = fmaf(w, f1.y, acc[3]);
    acc[4] = fmaf(w, f2.x, acc[4]); acc[5] = fmaf(w, f2.y, acc[5]);
    acc[6] = fmaf(w, f3.x, acc[6]); acc[7] = fmaf(w, f3.y, acc[7]);
}

// ---------------------------------------------------------------------------
// Kernel 0: row-CSR + col-CSR of (adj>0); col pass also scatters g_pos[m][n].
// ---------------------------------------------------------------------------
__global__ __launch_bounds__(1024) void k_csr(const float* __restrict__ adj) {
    const int tid  = threadIdx.x;
    const int lane = tid & 31;
    const int w    = tid >> 5;               // warp 0..31
    if (blockIdx.y == 0) {
        const int r = blockIdx.x * 32 + w;
        if (r >= NN) return;
        int cnt = 0;
        for (int m0 = 0; m0 < NN; m0 += 32) {
            int m = m0 + lane;
            float v = (m < NN) ? adj[r * NN + m] : 0.f;
            unsigned msk = __ballot_sync(0xffffffffu, v > 0.f);
            if (v > 0.f)
                g_row_idx[r * NN + cnt + __popc(msk & ((1u << lane) - 1u))] = m;
            cnt += __popc(msk);
        }
        if (lane == 0) g_row_cnt[r] = cnt;
    } else {
        __shared__ float tile[32][33];
        const int cbase = blockIdx.x * 32;
        const int c = cbase + w;              // this warp's column
        int cnt = 0;
        for (int n0 = 0; n0 < NN; n0 += 32) {
            int n = n0 + w, m = cbase + lane;
            tile[w][lane] = (n < NN && m < NN) ? adj[n * NN + m] : 0.f;
            __syncthreads();
            if (c < NN) {
                float v = tile[lane][w];
                unsigned msk = __ballot_sync(0xffffffffu, v > 0.f);
                if (v > 0.f) {
                    int p = cnt + __popc(msk & ((1u << lane) - 1u));
                    g_col_idx[c * NN + p] = n0 + lane;
                    g_pos[c * NN + n0 + lane] = p;
                }
                cnt += __popc(msk);
            }
            __syncthreads();
        }
        if (c < NN && lane == 0) g_col_cnt[c] = cnt;
    }
}

// ---------------------------------------------------------------------------
// Kernel 1: Wh = concat(ht,h)@W via tf32 mma (stored fp16); exact fp32 logits
// stored batch-minor as {val, exp(val)} pairs for separable softmax weights.
// ---------------------------------------------------------------------------
__global__ __launch_bounds__(128) void k_wh(const float* __restrict__ h,
                                            const float* __restrict__ ht,
                                            const float* __restrict__ W,
                                            const float* __restrict__ a) {
    const int b     = blockIdx.y;
    const int rbase = blockIdx.x * 64;
    const int tid   = threadIdx.x;

    __shared__ float xs[64 * XST];
    __shared__ float Ws[64 * XST];
    __shared__ float Wa[128];

    for (int k = tid; k < 1024; k += 128) {
        int i = k >> 4, c4 = (k & 15) * 4;
        *(float4*)&Ws[i * XST + c4] = *(const float4*)&W[i * 64 + c4];
    }
    for (int k = tid; k < 1024; k += 128) {
        int r = k >> 4, c4 = (k & 15) * 4;
        int gr = rbase + r;
        float4 v = make_float4(0.f, 0.f, 0.f, 0.f);
        if (gr < NN) {
            const float* src = (gr < NROW) ? &ht[((size_t)b * NROW + gr) * D]
                                           : &h [((size_t)b * NROW + gr - NROW) * D];
            v = *(const float4*)(src + c4);
        }
        *(float4*)&xs[r * XST + c4] = v;
    }
    __syncthreads();

    {   // Wa[0:64] = W@a[:64], Wa[64:128] = W@a[64:]
        int kk = tid & 63, which = tid >> 6;
        float s = 0.f;
        for (int c = 0; c < 64; c++)
            s = fmaf(Ws[kk * XST + c], a[which * 64 + c], s);
        Wa[which * 64 + kk] = s;
    }
    __syncthreads();

    const int warp = tid >> 5, lane = tid & 31;
    const int g = lane >> 2, t4 = lane & 3;
    const int m0 = warp * 16;
    float acc[8][4];
#pragma unroll
    for (int nt = 0; nt < 8; nt++)
#pragma unroll
        for (int j = 0; j < 4; j++) acc[nt][j] = 0.f;

#pragma unroll
    for (int ks = 0; ks < 64; ks += 8) {
        unsigned A0 = cvt_tf32(xs[(m0 + g)     * XST + ks + t4]);
        unsigned A1 = cvt_tf32(xs[(m0 + g + 8) * XST + ks + t4]);
        unsigned A2 = cvt_tf32(xs[(m0 + g)     * XST + ks + t4 + 4]);
        unsigned A3 = cvt_tf32(xs[(m0 + g + 8) * XST + ks + t4 + 4]);
#pragma unroll
        for (int nt = 0; nt < 8; nt++) {
            unsigned B0 = cvt_tf32(Ws[(ks + t4)     * XST + nt * 8 + g]);
            unsigned B1 = cvt_tf32(Ws[(ks + t4 + 4) * XST + nt * 8 + g]);
            mma_tf32(acc[nt], A0, A1, A2, A3, B0, B1);
        }
    }

#pragma unroll
    for (int nt = 0; nt < 8; nt++) {
        int col = nt * 8 + t4 * 2;
        int r0 = rbase + m0 + g, r1 = r0 + 8;
        __half2 h0 = __floats2half2_rn(acc[nt][0], acc[nt][1]);
        __half2 h1 = __floats2half2_rn(acc[nt][2], acc[nt][3]);
        if (r0 < NN) *(__half2*)&g_Whh[((size_t)b * NN + r0) * D + col] = h0;
        if (r1 < NN) *(__half2*)&g_Whh[((size_t)b * NN + r1) * D + col] = h1;
    }

    {   // Exact fp32 logits + their exps (separable softmax numerators)
        int r = tid & 63, which = tid >> 6;
        float s = 0.f;
#pragma unroll 4
        for (int k2 = 0; k2 < 64; k2++)
            s = fmaf(xs[r * XST + k2], Wa[which * 64 + k2], s);
        int gr = rbase + r;
        if (gr < NN) {
            float2 v = make_float2(s, __expf(s));
            if (which == 0) g_l1[gr * BATCH + b] = v;
            else            g_l2[gr * BATCH + b] = v;
        }
    }
}

// ---------------------------------------------------------------------------
// Kernel 2: normalized attention table — barrier-free, ILP-2.
// One column m per block, 64 threads (thread = batch b).
// ---------------------------------------------------------------------------
__global__ __launch_bounds__(64) void k_att() {
    const int m = blockIdx.x;
    const int b = threadIdx.x;               // 0..63
    const int cnt = g_col_cnt[m];
    const float2 l2 = g_l2[m * BATCH + b];
    const int* __restrict__ ci = &g_col_idx[m * NN];
    float* dst = &g_att[(size_t)m * MAXD * BATCH + b];

    float Z0 = 0.f, Z1 = 0.f;
    int p = 0;
    for (; p + 2 <= cnt; p += 2) {
        int n0 = __ldg(&ci[p]), n1 = __ldg(&ci[p + 1]);
        float2 a0 = g_l1[n0 * BATCH + b];
        float2 a1 = g_l1[n1 * BATCH + b];
        float s0 = a0.x + l2.x, s1 = a1.x + l2.x;
        float e0 = (s0 > 0.f) ? a0.y * l2.y : __expf(0.2f * s0);
        float e1 = (s1 > 0.f) ? a1.y * l2.y : __expf(0.2f * s1);
        dst[p * BATCH]       = e0;
        dst[(p + 1) * BATCH] = e1;
        Z0 += e0; Z1 += e1;
    }
    if (p < cnt) {
        float2 a0 = g_l1[__ldg(&ci[p]) * BATCH + b];
        float s0 = a0.x + l2.x;
        float e0 = (s0 > 0.f) ? a0.y * l2.y : __expf(0.2f * s0);
        dst[p * BATCH] = e0;
        Z0 += e0;
    }
    const float zi = 1.f / (Z0 + Z1);
    for (int q = 0; q < cnt; q++)
        dst[q * BATCH] *= zi;
}

// ---------------------------------------------------------------------------
// Kernel 3: h_prime[b,n,:] = sum_j att * Wh[b,m_j,:]; concat + ELU.
// Grid (614, 2) x 256 threads: block = (n, batch-half of 32), 8 lanes/b.
// Software-pipelined gather: batch k+1's loads issued before batch k's FMAs.
// ---------------------------------------------------------------------------
__global__ __launch_bounds__(256) void k_out(float* __restrict__ out) {
    const int n    = blockIdx.x;
    const int tid  = threadIdx.x;
    const int b    = (blockIdx.y << 5) + (tid >> 3);   // 0..63
    const int lane = tid & 7;
    const int cnt  = g_row_cnt[n];

    __shared__ int2 sjd[MAXD];        // {wh byte-off, att index base}
    if (tid < cnt) {
        int m = g_row_idx[n * NN + tid];
        int p = g_pos[m * NN + n];
        sjd[tid] = make_int2(m << 7, (m * MAXD + p) * BATCH);
    }
    __syncthreads();

    const char* whb = (const char*)g_Whh + (size_t)b * NN * 128 + lane * 16;

    float acc[8];
#pragma unroll
    for (int k = 0; k < 8; k++) acc[k] = 0.f;

    float w[4]; uint4 r[4];
    const int nb = cnt >> 2;          // full batches of 4

    if (nb > 0) {
        // prologue: load batch 0
#pragma unroll
        for (int u = 0; u < 4; u++) {
            int2 d = sjd[u];
            w[u] = g_att[d.y + b];
            r[u] = *(const uint4*)(whb + d.x);
        }
        for (int kb = 1; kb < nb; kb++) {
            float wn[4]; uint4 rn[4];
#pragma unroll
            for (int u = 0; u < 4; u++) {       // issue next batch's loads
                int2 d = sjd[kb * 4 + u];
                wn[u] = g_att[d.y + b];
                rn[u] = *(const uint4*)(whb + d.x);
            }
#pragma unroll
            for (int u = 0; u < 4; u++) fma8(acc, w[u], r[u]);
#pragma unroll
            for (int u = 0; u < 4; u++) { w[u] = wn[u]; r[u] = rn[u]; }
        }
#pragma unroll
        for (int u = 0; u < 4; u++) fma8(acc, w[u], r[u]);
    }
    for (int j = nb << 2; j < cnt; j++) {
        int2 d = sjd[j];
        float wj = g_att[d.y + b];
        uint4 rj = *(const uint4*)(whb + d.x);
        fma8(acc, wj, rj);
    }

#pragma unroll
    for (int k = 0; k < 8; k++)
        acc[k] = (acc[k] > 0.f) ? acc[k] : (__expf(acc[k]) - 1.f);

    size_t ob = (n < NROW) ? (((size_t)b * NROW + n) * 128 + lane * 8)
                           : (((size_t)b * NROW + (n - NROW)) * 128 + 64 + lane * 8);
    *(float4*)(out + ob)     = make_float4(acc[0], acc[1], acc[2], acc[3]);
    *(float4*)(out + ob + 4) = make_float4(acc[4], acc[5], acc[6], acc[7]);
}

// ---------------------------------------------------------------------------
extern "C" void kernel_launch(void* const* d_in, const int* in_sizes, int n_in,
                              void* d_out, int out_size) {
    const float* h   = (const float*)d_in[0];
    const float* ht  = (const float*)d_in[1];
    const float* W   = (const float*)d_in[2];
    const float* a   = (const float*)d_in[3];
    const float* adj = (const float*)d_in[4];
    float* out = (float*)d_out;

    k_csr<<<dim3((NN + 31) / 32, 2), 1024>>>(adj);
    k_wh<<<dim3((NN + 63) / 64, BATCH), 128>>>(h, ht, W, a);
    k_att<<<NN, 64>>>();
    k_out<<<dim3(NN, 2), 256>>>(out);
}